// round 16
// baseline (speedup 1.0000x reference)
#include <cuda_runtime.h>
#include <cuda_fp16.h>
#include <cstdint>

#define BATCH 8
#define NN 4096
#define FF 128
#define UU 64
#define LOG2E 1.4426950408889634f
#define XSTR 36   // gat: Xs row stride in half2 words
#define PSTR 36   // gat: Ps row stride in half2 words

// ---------------- device scratch (no allocations allowed) -------------------
__device__ __half  g_XTh[BATCH * UU * NN];   // X^T per batch, fp16
__device__ float2  g_es2[BATCH * NN];        // (2^s~, 2^{0.2 s~})
__device__ float2  g_et2[BATCH * NN];        // (2^t~, 2^{0.2 t~})
__device__ float2  g_w12[FF];                // (W@a1, W@a2) per k

// ---------------- helpers ---------------------------------------------------
__device__ __forceinline__ float ex2f(float x) {
    float r; asm("ex2.approx.f32 %0, %1;" : "=f"(r) : "f"(x)); return r;
}
__device__ __forceinline__ void ldsm4(uint32_t& r0, uint32_t& r1, uint32_t& r2,
                                      uint32_t& r3, uint32_t a) {
    asm volatile("ldmatrix.sync.aligned.m8n8.x4.shared.b16 {%0,%1,%2,%3}, [%4];"
                 : "=r"(r0), "=r"(r1), "=r"(r2), "=r"(r3) : "r"(a));
}
__device__ __forceinline__ uint32_t packh2(float a, float b) {
    __half2 h = __floats2half2_rn(a, b);
    return *(uint32_t*)&h;
}
#define CP_COMMIT() asm volatile("cp.async.commit_group;" ::: "memory")
#define CP_WAIT(n)  asm volatile("cp.async.wait_group %0;" :: "n"(n) : "memory")
__device__ __forceinline__ void cp16(uint32_t dst, const void* src) {
    asm volatile("cp.async.cg.shared.global [%0], [%1], 16;"
                 :: "r"(dst), "l"(src) : "memory");
}

// ---------------------------------------------------------------------------
// Kernel 0: w1 = W@a1, w2 = W@a2  (one CTA, 128 threads)
// ---------------------------------------------------------------------------
__global__ void wk_kernel(const float* __restrict__ W, const float* __restrict__ a1,
                          const float* __restrict__ a2) {
    int k = threadIdx.x;
    float s1 = 0.f, s2 = 0.f;
#pragma unroll 16
    for (int u = 0; u < UU; ++u) {
        float wv = W[k * UU + u];
        s1 += wv * a1[u];
        s2 += wv * a2[u];
    }
    g_w12[k] = make_float2(s1, s2);
}

// ---------------------------------------------------------------------------
// Kernel 1: s~,t~ from fp32 H directly (full precision path).
// ---------------------------------------------------------------------------
__global__ void __launch_bounds__(256) st2_kernel(const float* __restrict__ H) {
    const int w = threadIdx.x >> 5, lane = threadIdx.x & 31;
    const int gw = blockIdx.x * 8 + w;
    float2 w0 = g_w12[lane], w1v = g_w12[lane + 32];
    float2 w2v = g_w12[lane + 64], w3 = g_w12[lane + 96];
#pragma unroll
    for (int i = 0; i < 8; ++i) {
        const int row = gw * 8 + i;
        const float* Hp = H + (size_t)row * FF;
        float h0 = Hp[lane], h1 = Hp[lane + 32], h2 = Hp[lane + 64], h3 = Hp[lane + 96];
        float sv = h0 * w0.x + h1 * w1v.x + h2 * w2v.x + h3 * w3.x;
        float tv = h0 * w0.y + h1 * w1v.y + h2 * w2v.y + h3 * w3.y;
#pragma unroll
        for (int o = 16; o; o >>= 1) {
            sv += __shfl_xor_sync(0xffffffffu, sv, o);
            tv += __shfl_xor_sync(0xffffffffu, tv, o);
        }
        if (lane == 0) {
            sv *= LOG2E; tv *= LOG2E;
            g_es2[row] = make_float2(ex2f(sv), ex2f(0.2f * sv));
            g_et2[row] = make_float2(ex2f(tv), ex2f(0.2f * tv));
        }
    }
}

// ---------------------------------------------------------------------------
// Kernel 2: X^T (fp16) = (H @ W)^T via m16n8k16 MMA (passing R14 version).
// ---------------------------------------------------------------------------
#define XG_HW 68
#define XG_WT (128 * XG_HW)
#define XG_SMEM ((XG_WT + 64 * XG_HW) * 4)

__global__ void __launch_bounds__(256) xgemm16_kernel(const float* __restrict__ H,
                                                      const float* __restrict__ W) {
    extern __shared__ uint32_t smw[];
    __half* Wth = (__half*)(smw + XG_WT);
    const uint32_t smbase = (uint32_t)__cvta_generic_to_shared(smw);

    const int row0 = blockIdx.x * 128;
    const int t = threadIdx.x;
    const int w = t >> 5, lane = t & 31;
    const int g = lane >> 2, tig = lane & 3;
    const int m0 = w * 16;

#pragma unroll
    for (int q = 0; q < 16; ++q) {
        int idx = t + q * 256;
        int r = idx >> 5, c4 = idx & 31;
        float4 v = *(const float4*)(H + (size_t)(row0 + r) * FF + c4 * 4);
        *(uint2*)&smw[r * XG_HW + c4 * 2] = make_uint2(packh2(v.x, v.y), packh2(v.z, v.w));
    }
#pragma unroll
    for (int q = 0; q < 32; ++q) {
        int idx = t + q * 256;
        int k = idx >> 6, u = idx & 63;
        Wth[u * 136 + k] = __float2half_rn(W[idx]);
    }
    __syncthreads();

    float4 acc[8];
#pragma unroll
    for (int nb = 0; nb < 8; ++nb) acc[nb] = make_float4(0.f, 0.f, 0.f, 0.f);

    const uint32_t aofs = ((uint32_t)(((lane >> 3) & 1) * 8 + (lane & 7))) * 272
                        + ((uint32_t)(lane >> 4)) * 16;
    const uint32_t bofs = ((uint32_t)((lane >> 4) * 8 + (lane & 7))) * 272
                        + ((uint32_t)((lane >> 3) & 1)) * 16;
    const uint32_t pa = smbase + m0 * 272 + aofs;
    const uint32_t pb = smbase + XG_WT * 4 + bofs;

#pragma unroll
    for (int kc = 0; kc < 8; ++kc) {
        uint32_t a0, a1, a2v, a3;
        ldsm4(a0, a1, a2v, a3, pa + kc * 32);
#pragma unroll
        for (int pr = 0; pr < 4; ++pr) {
            uint32_t b0, b1, b2, b3;
            ldsm4(b0, b1, b2, b3, pb + pr * (16 * 272) + kc * 32);
            asm volatile(
                "mma.sync.aligned.m16n8k16.row.col.f32.f16.f16.f32 "
                "{%0,%1,%2,%3}, {%4,%5,%6,%7}, {%8,%9}, {%0,%1,%2,%3};\n"
                : "+f"(acc[2 * pr].x), "+f"(acc[2 * pr].y),
                  "+f"(acc[2 * pr].z), "+f"(acc[2 * pr].w)
                : "r"(a0), "r"(a1), "r"(a2v), "r"(a3), "r"(b0), "r"(b1));
            asm volatile(
                "mma.sync.aligned.m16n8k16.row.col.f32.f16.f16.f32 "
                "{%0,%1,%2,%3}, {%4,%5,%6,%7}, {%8,%9}, {%0,%1,%2,%3};\n"
                : "+f"(acc[2 * pr + 1].x), "+f"(acc[2 * pr + 1].y),
                  "+f"(acc[2 * pr + 1].z), "+f"(acc[2 * pr + 1].w)
                : "r"(a0), "r"(a1), "r"(a2v), "r"(a3), "r"(b2), "r"(b3));
        }
    }
    __syncthreads();

    __half* Xsm = (__half*)smw;
#pragma unroll
    for (int nb = 0; nb < 8; ++nb) {
        int n = nb * 8 + tig * 2;
        Xsm[n * 136 + m0 + g] = __float2half_rn(acc[nb].x);
        Xsm[(n + 1) * 136 + m0 + g] = __float2half_rn(acc[nb].y);
        Xsm[n * 136 + m0 + g + 8] = __float2half_rn(acc[nb].z);
        Xsm[(n + 1) * 136 + m0 + g + 8] = __float2half_rn(acc[nb].w);
    }
    __syncthreads();

    const int bb = row0 >> 12, n0 = row0 & (NN - 1);
#pragma unroll
    for (int q = 0; q < 4; ++q) {
        int idx = t + q * 256;
        int u = idx >> 4, ch = idx & 15;
        uint4 v = *(uint4*)&smw[u * XG_HW + ch * 4];
        *(uint4*)(g_XTh + ((size_t)bb * UU + u) * NN + n0 + ch * 8) = v;
    }
}

// ---------------------------------------------------------------------------
// Kernel 3: gat with 2-stage cp.async A ring + 3-stage X ring, single Ps.
// Grid (32, 8). CTA = 256 thr (8 warps); warp w owns rows [16w, 16w+16).
// iter k: wait G_{k-1}; barrier; issue G_k={A(k+2),X(k+2)}; MMA(k);
//         syncwarp; P-stage(k+1) from A-smem.
// ---------------------------------------------------------------------------
#define OFF_A 0                         // 2 stages x 8192 words (32KB)
#define OFF_X 16384                     // 3 stages x 2304 words
#define OFF_P (OFF_X + 3 * 2304)        // 23296: 128 x PSTR words
#define OFF_Z (OFF_P + 128 * PSTR)      // 27904
#define OFF_E (OFF_Z + 128)             // 28032 (float2 x 128)
#define SMEM_GAT ((OFF_E + 256) * 4)    // 113152 B

__global__ void __launch_bounds__(256, 2) gat_kernel(const float* __restrict__ A,
                                                     float* __restrict__ out) {
    extern __shared__ float sm[];
    uint32_t* PsW = (uint32_t*)sm + OFF_P;
    float* Zs = sm + OFF_Z;
    float2* Es2 = (float2*)(sm + OFF_E);
    const uint32_t smbase = (uint32_t)__cvta_generic_to_shared(sm);

    const int b = blockIdx.y;
    const int i0 = blockIdx.x * 128;
    const int tid = threadIdx.x;
    const int w = tid >> 5, lane = tid & 31;
    const int g = lane >> 2, tig = lane & 3;
    const int h = lane >> 4, c = lane & 15;
    const int wrow0 = i0 + w * 16;

    const uint32_t aofs = ((uint32_t)(((lane >> 3) & 1) * 8 + (lane & 7))) * (PSTR * 4)
                        + ((uint32_t)(lane >> 4)) * 16;
    const uint32_t bofs = ((uint32_t)((lane >> 4) * 8 + (lane & 7))) * (XSTR * 4)
                        + ((uint32_t)((lane >> 3) & 1)) * 16;
    const uint32_t pa = smbase + (OFF_P + w * 16 * PSTR) * 4 + aofs;

    if (tid < 128) Es2[tid] = g_es2[(size_t)b * NN + i0 + tid];

    float4 acc[8];
#pragma unroll
    for (int nb = 0; nb < 8; ++nb) acc[nb] = make_float4(0.f, 0.f, 0.f, 0.f);
    float zp[8];
#pragma unroll
    for (int it = 0; it < 8; ++it) zp[it] = 0.f;

    const float* Agm = A + ((size_t)b * NN + i0) * NN;      // CTA A-tile base
    const float2* etb = g_et2 + (size_t)b * NN + 4 * c;
    const __half* XTb = g_XTh + (size_t)b * UU * NN;
    const float2* Esw = Es2 + w * 16 + 8 * h;

    // issue helpers (each thread: 8 A-chunks, 2 X-chunks of 16B)
#define ISSUE_A(jt, slot) do {                                                  \
        const float* _s = Agm + (size_t)(jt) * 64;                              \
        uint32_t _d = smbase + (OFF_A + (slot) * 8192) * 4;                     \
        _Pragma("unroll")                                                       \
        for (int q = 0; q < 8; ++q) {                                           \
            int id = tid + q * 256; int r = id >> 4, s4 = id & 15;              \
            cp16(_d + (uint32_t)(r * 64 + s4 * 4) * 4,                          \
                 _s + (size_t)r * NN + s4 * 4);                                 \
        } } while (0)
#define ISSUE_X(jt, xs) do {                                                    \
        const __half* _s = XTb + (size_t)(jt) * 64;                             \
        uint32_t _d = smbase + (OFF_X + (xs) * 2304) * 4;                       \
        _Pragma("unroll")                                                       \
        for (int q = 0; q < 2; ++q) {                                           \
            int id = tid + q * 256; int u = id >> 3, ch = id & 7;               \
            cp16(_d + (uint32_t)(u * XSTR + ch * 4) * 4,                        \
                 _s + (size_t)u * NN + ch * 8);                                 \
        } } while (0)
#define PSTAGE(jt, slot) do {                                                   \
        const int _j = (jt) * 64;                                               \
        float4 et01 = *(const float4*)(etb + _j);                               \
        float4 et23 = *(const float4*)(etb + _j + 2);                           \
        const float* As = sm + OFF_A + (slot) * 8192 + (w * 16 + 8 * h) * 64 + 4 * c; \
        _Pragma("unroll")                                                       \
        for (int it = 0; it < 8; ++it) {                                        \
            float4 m = *(const float4*)(As + it * 64);                          \
            float2 ef = Esw[it];                                                \
            float e0 = m.x * fmaxf(ef.x * et01.x, ef.y * et01.y);               \
            float e1 = m.y * fmaxf(ef.x * et01.z, ef.y * et01.w);               \
            float e2 = m.z * fmaxf(ef.x * et23.x, ef.y * et23.y);               \
            float e3 = m.w * fmaxf(ef.x * et23.z, ef.y * et23.w);               \
            zp[it] += (e0 + e1) + (e2 + e3);                                    \
            *(uint2*)&PsW[(8 * h + it + w * 16) * PSTR + 2 * c] =               \
                make_uint2(packh2(e0, e1), packh2(e2, e3));                     \
        } } while (0)

    // ---- prologue ----
    ISSUE_A(0, 0); ISSUE_X(0, 0); CP_COMMIT();      // G_a
    ISSUE_A(1, 1); ISSUE_X(1, 1); CP_COMMIT();      // G_b
    CP_WAIT(1);                                     // G_a done
    __syncthreads();                                // A(0),X(0),Es2 visible
    PSTAGE(0, 0);                                   // P(0) -> Ps (warp-private)

    // ---- main loop ----
    int xcur = 0, xnxt2 = 2;                        // k%3, (k+2)%3
    for (int k = 0; k < 64; ++k) {
        CP_WAIT(0);                                 // A(k+1), X(k+1) arrived
        __syncthreads();
        if (k < 62) {
            ISSUE_A(k + 2, k & 1);
            ISSUE_X(k + 2, xnxt2);
            CP_COMMIT();
        }

        // --- MMA(k) on Xs[xcur] + Ps ---
        {
            const uint32_t pb = smbase + (OFF_X + xcur * 2304) * 4 + bofs;
#pragma unroll
            for (int kc = 0; kc < 4; ++kc) {
                uint32_t a0, a1, a2v, a3;
                ldsm4(a0, a1, a2v, a3, pa + kc * 32);
#pragma unroll
                for (int pr = 0; pr < 4; ++pr) {
                    uint32_t b0, b1, b2, b3;
                    ldsm4(b0, b1, b2, b3, pb + pr * (16 * XSTR * 4) + kc * 32);
                    asm volatile(
                        "mma.sync.aligned.m16n8k16.row.col.f32.f16.f16.f32 "
                        "{%0,%1,%2,%3}, {%4,%5,%6,%7}, {%8,%9}, {%0,%1,%2,%3};\n"
                        : "+f"(acc[2 * pr].x), "+f"(acc[2 * pr].y),
                          "+f"(acc[2 * pr].z), "+f"(acc[2 * pr].w)
                        : "r"(a0), "r"(a1), "r"(a2v), "r"(a3), "r"(b0), "r"(b1));
                    asm volatile(
                        "mma.sync.aligned.m16n8k16.row.col.f32.f16.f16.f32 "
                        "{%0,%1,%2,%3}, {%4,%5,%6,%7}, {%8,%9}, {%0,%1,%2,%3};\n"
                        : "+f"(acc[2 * pr + 1].x), "+f"(acc[2 * pr + 1].y),
                          "+f"(acc[2 * pr + 1].z), "+f"(acc[2 * pr + 1].w)
                        : "r"(a0), "r"(a1), "r"(a2v), "r"(a3), "r"(b2), "r"(b3));
                }
            }
        }
        __syncwarp();          // warp's ldmatrix of Ps done before overwrite

        if (k < 63) PSTAGE(k + 1, (k + 1) & 1);

        if (++xcur == 3) xcur = 0;
        if (++xnxt2 == 3) xnxt2 = 0;
    }

    // --- Z reduction ---
#pragma unroll
    for (int it = 0; it < 8; ++it) {
        float v = zp[it];
#pragma unroll
        for (int o = 8; o; o >>= 1) v += __shfl_xor_sync(0xffffffffu, v, o);
        if (c == 0) Zs[w * 16 + 8 * h + it] = v;
    }
    __syncwarp();

    // --- epilogue: relu(D / Z) ---
    float inv0 = 1.0f / Zs[w * 16 + g];
    float inv1 = 1.0f / Zs[w * 16 + g + 8];
    float* outb = out + ((size_t)b * NN + wrow0) * UU;
#pragma unroll
    for (int nb = 0; nb < 8; ++nb) {
        int col = nb * 8 + tig * 2;
        float2 v0 = make_float2(fmaxf(acc[nb].x * inv0, 0.f), fmaxf(acc[nb].y * inv0, 0.f));
        float2 v1 = make_float2(fmaxf(acc[nb].z * inv1, 0.f), fmaxf(acc[nb].w * inv1, 0.f));
        *(float2*)(outb + (size_t)g * UU + col) = v0;
        *(float2*)(outb + (size_t)(g + 8) * UU + col) = v1;
    }
#undef ISSUE_A
#undef ISSUE_X
#undef PSTAGE
}

// ---------------------------------------------------------------------------
extern "C" void kernel_launch(void* const* d_in, const int* in_sizes, int n_in,
                              void* d_out, int out_size) {
    const float* H = (const float*)d_in[0];       // [8,4096,128]
    const float* Amask = (const float*)d_in[1];   // [8,4096,4096]
    const float* W = (const float*)d_in[2];       // [128,64]
    const float* a1 = (const float*)d_in[3];      // [64,1]
    const float* a2 = (const float*)d_in[4];      // [64,1]
    float* out = (float*)d_out;                   // [8,4096,64]

    cudaFuncSetAttribute(xgemm16_kernel, cudaFuncAttributeMaxDynamicSharedMemorySize, XG_SMEM);
    cudaFuncSetAttribute(gat_kernel, cudaFuncAttributeMaxDynamicSharedMemorySize, SMEM_GAT);

    wk_kernel<<<1, 128>>>(W, a1, a2);
    st2_kernel<<<512, 256>>>(H);
    xgemm16_kernel<<<(BATCH * NN) / 128, 256, XG_SMEM>>>(H, W);
    gat_kernel<<<dim3(NN / 128, BATCH), 256, SMEM_GAT>>>(Amask, out);
}

// round 17
// speedup vs baseline: 1.4769x; 1.4769x over previous
#include <cuda_runtime.h>
#include <cuda_fp16.h>
#include <cstdint>

#define BATCH 8
#define NN 4096
#define FF 128
#define UU 64
#define LOG2E 1.4426950408889634f
#define XSTR 36   // gat: Xs row stride in half2 words
#define PSTR 36   // gat: Ps row stride in half2 words

// ---------------- device scratch (no allocations allowed) -------------------
__device__ __half  g_XTh[BATCH * UU * NN];   // X^T per batch, fp16
__device__ float2  g_es2[BATCH * NN];        // (2^s~, 2^{0.2 s~})
__device__ float2  g_et2[BATCH * NN];        // (2^t~, 2^{0.2 t~})
__device__ float2  g_w12[FF];                // (W@a1, W@a2) per k

// ---------------- helpers ---------------------------------------------------
__device__ __forceinline__ float ex2f(float x) {
    float r; asm("ex2.approx.f32 %0, %1;" : "=f"(r) : "f"(x)); return r;
}
__device__ __forceinline__ void ldsm4(uint32_t& r0, uint32_t& r1, uint32_t& r2,
                                      uint32_t& r3, uint32_t a) {
    asm volatile("ldmatrix.sync.aligned.m8n8.x4.shared.b16 {%0,%1,%2,%3}, [%4];"
                 : "=r"(r0), "=r"(r1), "=r"(r2), "=r"(r3) : "r"(a));
}
__device__ __forceinline__ uint32_t packh2(float a, float b) {
    __half2 h = __floats2half2_rn(a, b);
    return *(uint32_t*)&h;
}
#define CP_COMMIT() asm volatile("cp.async.commit_group;" ::: "memory")
#define CP_WAIT(n)  asm volatile("cp.async.wait_group %0;" :: "n"(n) : "memory")
__device__ __forceinline__ void cp16(uint32_t dst, const void* src) {
    asm volatile("cp.async.cg.shared.global [%0], [%1], 16;"
                 :: "r"(dst), "l"(src) : "memory");
}

// ---------------------------------------------------------------------------
// Kernel 0: w1 = W@a1, w2 = W@a2  (one CTA, 128 threads)
// ---------------------------------------------------------------------------
__global__ void wk_kernel(const float* __restrict__ W, const float* __restrict__ a1,
                          const float* __restrict__ a2) {
    int k = threadIdx.x;
    float s1 = 0.f, s2 = 0.f;
#pragma unroll 16
    for (int u = 0; u < UU; ++u) {
        float wv = W[k * UU + u];
        s1 += wv * a1[u];
        s2 += wv * a2[u];
    }
    g_w12[k] = make_float2(s1, s2);
}

// ---------------------------------------------------------------------------
// Kernel 1: s~,t~ from fp32 H directly (full precision path).
// ---------------------------------------------------------------------------
__global__ void __launch_bounds__(256) st2_kernel(const float* __restrict__ H) {
    const int w = threadIdx.x >> 5, lane = threadIdx.x & 31;
    const int gw = blockIdx.x * 8 + w;
    float2 w0 = g_w12[lane], w1v = g_w12[lane + 32];
    float2 w2v = g_w12[lane + 64], w3 = g_w12[lane + 96];
#pragma unroll
    for (int i = 0; i < 8; ++i) {
        const int row = gw * 8 + i;
        const float* Hp = H + (size_t)row * FF;
        float h0 = Hp[lane], h1 = Hp[lane + 32], h2 = Hp[lane + 64], h3 = Hp[lane + 96];
        float sv = h0 * w0.x + h1 * w1v.x + h2 * w2v.x + h3 * w3.x;
        float tv = h0 * w0.y + h1 * w1v.y + h2 * w2v.y + h3 * w3.y;
#pragma unroll
        for (int o = 16; o; o >>= 1) {
            sv += __shfl_xor_sync(0xffffffffu, sv, o);
            tv += __shfl_xor_sync(0xffffffffu, tv, o);
        }
        if (lane == 0) {
            sv *= LOG2E; tv *= LOG2E;
            g_es2[row] = make_float2(ex2f(sv), ex2f(0.2f * sv));
            g_et2[row] = make_float2(ex2f(tv), ex2f(0.2f * tv));
        }
    }
}

// ---------------------------------------------------------------------------
// Kernel 2: X^T (fp16) = (H @ W)^T via m16n8k16 MMA (passing R14 version).
// ---------------------------------------------------------------------------
#define XG_HW 68
#define XG_WT (128 * XG_HW)
#define XG_SMEM ((XG_WT + 64 * XG_HW) * 4)

__global__ void __launch_bounds__(256) xgemm16_kernel(const float* __restrict__ H,
                                                      const float* __restrict__ W) {
    extern __shared__ uint32_t smw[];
    __half* Wth = (__half*)(smw + XG_WT);
    const uint32_t smbase = (uint32_t)__cvta_generic_to_shared(smw);

    const int row0 = blockIdx.x * 128;
    const int t = threadIdx.x;
    const int w = t >> 5, lane = t & 31;
    const int g = lane >> 2, tig = lane & 3;
    const int m0 = w * 16;

#pragma unroll
    for (int q = 0; q < 16; ++q) {
        int idx = t + q * 256;
        int r = idx >> 5, c4 = idx & 31;
        float4 v = *(const float4*)(H + (size_t)(row0 + r) * FF + c4 * 4);
        *(uint2*)&smw[r * XG_HW + c4 * 2] = make_uint2(packh2(v.x, v.y), packh2(v.z, v.w));
    }
#pragma unroll
    for (int q = 0; q < 32; ++q) {
        int idx = t + q * 256;
        int k = idx >> 6, u = idx & 63;
        Wth[u * 136 + k] = __float2half_rn(W[idx]);
    }
    __syncthreads();

    float4 acc[8];
#pragma unroll
    for (int nb = 0; nb < 8; ++nb) acc[nb] = make_float4(0.f, 0.f, 0.f, 0.f);

    const uint32_t aofs = ((uint32_t)(((lane >> 3) & 1) * 8 + (lane & 7))) * 272
                        + ((uint32_t)(lane >> 4)) * 16;
    const uint32_t bofs = ((uint32_t)((lane >> 4) * 8 + (lane & 7))) * 272
                        + ((uint32_t)((lane >> 3) & 1)) * 16;
    const uint32_t pa = smbase + m0 * 272 + aofs;
    const uint32_t pb = smbase + XG_WT * 4 + bofs;

#pragma unroll
    for (int kc = 0; kc < 8; ++kc) {
        uint32_t a0, a1, a2v, a3;
        ldsm4(a0, a1, a2v, a3, pa + kc * 32);
#pragma unroll
        for (int pr = 0; pr < 4; ++pr) {
            uint32_t b0, b1, b2, b3;
            ldsm4(b0, b1, b2, b3, pb + pr * (16 * 272) + kc * 32);
            asm volatile(
                "mma.sync.aligned.m16n8k16.row.col.f32.f16.f16.f32 "
                "{%0,%1,%2,%3}, {%4,%5,%6,%7}, {%8,%9}, {%0,%1,%2,%3};\n"
                : "+f"(acc[2 * pr].x), "+f"(acc[2 * pr].y),
                  "+f"(acc[2 * pr].z), "+f"(acc[2 * pr].w)
                : "r"(a0), "r"(a1), "r"(a2v), "r"(a3), "r"(b0), "r"(b1));
            asm volatile(
                "mma.sync.aligned.m16n8k16.row.col.f32.f16.f16.f32 "
                "{%0,%1,%2,%3}, {%4,%5,%6,%7}, {%8,%9}, {%0,%1,%2,%3};\n"
                : "+f"(acc[2 * pr + 1].x), "+f"(acc[2 * pr + 1].y),
                  "+f"(acc[2 * pr + 1].z), "+f"(acc[2 * pr + 1].w)
                : "r"(a0), "r"(a1), "r"(a2v), "r"(a3), "r"(b2), "r"(b3));
        }
    }
    __syncthreads();

    __half* Xsm = (__half*)smw;
#pragma unroll
    for (int nb = 0; nb < 8; ++nb) {
        int n = nb * 8 + tig * 2;
        Xsm[n * 136 + m0 + g] = __float2half_rn(acc[nb].x);
        Xsm[(n + 1) * 136 + m0 + g] = __float2half_rn(acc[nb].y);
        Xsm[n * 136 + m0 + g + 8] = __float2half_rn(acc[nb].z);
        Xsm[(n + 1) * 136 + m0 + g + 8] = __float2half_rn(acc[nb].w);
    }
    __syncthreads();

    const int bb = row0 >> 12, n0 = row0 & (NN - 1);
#pragma unroll
    for (int q = 0; q < 4; ++q) {
        int idx = t + q * 256;
        int u = idx >> 4, ch = idx & 15;
        uint4 v = *(uint4*)&smw[u * XG_HW + ch * 4];
        *(uint4*)(g_XTh + ((size_t)bb * UU + u) * NN + n0 + ch * 8) = v;
    }
}

// ---------------------------------------------------------------------------
// Kernel 3: gat. A via PER-THREAD cp.async 2-slot ring (each thread copies
// exactly the chunks it later reads -> wait_group only, no barrier on A).
// X via LDG + deferred STS (R14 scheme). Ps single-buffered (MMA -> syncwarp
// -> PSTAGE within an iteration). One __syncthreads per tile (for Xs).
// ---------------------------------------------------------------------------
#define OFF_A 0                          // 2 slots x 8192 words (64KB)
#define OFF_X (2 * 8192)                 // 2 slots x 2304 words
#define OFF_P (OFF_X + 2 * 2304)         // 128 x PSTR words
#define OFF_Z (OFF_P + 128 * PSTR)
#define OFF_E (OFF_Z + 128)              // float2 x 128
#define SMEM_GAT ((OFF_E + 256) * 4)     // 103936 B

__global__ void __launch_bounds__(256, 2) gat_kernel(const float* __restrict__ A,
                                                     float* __restrict__ out) {
    extern __shared__ float sm[];
    uint32_t* PsW = (uint32_t*)sm + OFF_P;
    float* Zs = sm + OFF_Z;
    float2* Es2 = (float2*)(sm + OFF_E);
    const uint32_t smbase = (uint32_t)__cvta_generic_to_shared(sm);

    const int b = blockIdx.y;
    const int i0 = blockIdx.x * 128;
    const int tid = threadIdx.x;
    const int w = tid >> 5, lane = tid & 31;
    const int g = lane >> 2, tig = lane & 3;
    const int h = lane >> 4, c = lane & 15;
    const int wrow0 = i0 + w * 16;

    const uint32_t aofs = ((uint32_t)(((lane >> 3) & 1) * 8 + (lane & 7))) * (PSTR * 4)
                        + ((uint32_t)(lane >> 4)) * 16;
    const uint32_t bofs = ((uint32_t)((lane >> 4) * 8 + (lane & 7))) * (XSTR * 4)
                        + ((uint32_t)((lane >> 3) & 1)) * 16;
    const uint32_t pa = smbase + (OFF_P + w * 16 * PSTR) * 4 + aofs;

    // this thread's private A rows/cols: rows w*16+8h+it (it=0..7), col 4c
    const int arow = w * 16 + 8 * h;                 // first of 8 rows
    const float* Asrc = A + ((size_t)b * NN + i0 + arow) * NN + 4 * c;
    const uint32_t Adst = smbase + (OFF_A + arow * 64 + 4 * c) * 4;  // + slot*8192w + it*64w
    const float* Ards = sm + OFF_A + arow * 64 + 4 * c;

    const int u0 = tid >> 3, ch0 = tid & 7;
    const int u1 = (tid + 256) >> 3, ch1 = tid & 7;

    if (tid < 128) Es2[tid] = g_es2[(size_t)b * NN + i0 + tid];

    float4 acc[8];
#pragma unroll
    for (int nb = 0; nb < 8; ++nb) acc[nb] = make_float4(0.f, 0.f, 0.f, 0.f);
    float zp[8];
#pragma unroll
    for (int it = 0; it < 8; ++it) zp[it] = 0.f;

    const float2* etb = g_et2 + (size_t)b * NN + 4 * c;
    const __half* XTb = g_XTh + (size_t)b * UU * NN;
    const float2* Esw = Es2 + w * 16 + 8 * h;

#define ISSUE_A(jt, slot) do {                                                  \
        const float* _s = Asrc + (size_t)(jt) * 64;                             \
        uint32_t _d = Adst + (uint32_t)(slot) * 32768;                          \
        _Pragma("unroll")                                                       \
        for (int it = 0; it < 8; ++it)                                          \
            cp16(_d + it * 256, _s + (size_t)it * NN);                          \
        CP_COMMIT(); } while (0)

#define PSTAGE(jt, slot) do {                                                   \
        const int _j = (jt) * 64;                                               \
        float4 et01 = *(const float4*)(etb + _j);                               \
        float4 et23 = *(const float4*)(etb + _j + 2);                           \
        const float* _a = Ards + (slot) * 8192;                                 \
        _Pragma("unroll")                                                       \
        for (int it = 0; it < 8; ++it) {                                        \
            float4 m = *(const float4*)(_a + it * 64);                          \
            float2 ef = Esw[it];                                                \
            float e0 = m.x * fmaxf(ef.x * et01.x, ef.y * et01.y);               \
            float e1 = m.y * fmaxf(ef.x * et01.z, ef.y * et01.w);               \
            float e2 = m.z * fmaxf(ef.x * et23.x, ef.y * et23.y);               \
            float e3 = m.w * fmaxf(ef.x * et23.z, ef.y * et23.w);               \
            zp[it] += (e0 + e1) + (e2 + e3);                                    \
            *(uint2*)&PsW[(arow + it) * PSTR + 2 * c] =                         \
                make_uint2(packh2(e0, e1), packh2(e2, e3));                     \
        } } while (0)

    // ---- prologue ----
    ISSUE_A(0, 0);                        // group A(0)
    ISSUE_A(1, 1);                        // group A(1)
    uint4 xv0 = *(const uint4*)(XTb + (size_t)u0 * NN + ch0 * 8);
    uint4 xv1 = *(const uint4*)(XTb + (size_t)u1 * NN + ch1 * 8);
    *(uint4*)((uint32_t*)sm + OFF_X + u0 * XSTR + ch0 * 4) = xv0;
    *(uint4*)((uint32_t*)sm + OFF_X + u1 * XSTR + ch1 * 4) = xv1;
    __syncthreads();                      // Es2 + Xs(0) visible
    CP_WAIT(1);                           // own A(0) chunks arrived
    PSTAGE(0, 0);                         // P(0) -> Ps (warp-private)
    __syncwarp();

    // ---- main loop ----
    for (int jt = 0; jt < 64; ++jt) {
        const int cur = jt & 1, nxt = cur ^ 1;

        if (jt < 62) ISSUE_A(jt + 2, cur);            // into slot jt%2 (free)
        if (jt < 63) {                                // X loads for jt+1
            const int j1 = (jt + 1) * 64;
            xv0 = *(const uint4*)(XTb + (size_t)u0 * NN + j1 + ch0 * 8);
            xv1 = *(const uint4*)(XTb + (size_t)u1 * NN + j1 + ch1 * 8);
        }

        // --- MMA(jt) on Xs[cur] + Ps ---
        {
            const uint32_t pb = smbase + (OFF_X + cur * 2304) * 4 + bofs;
#pragma unroll
            for (int kc = 0; kc < 4; ++kc) {
                uint32_t a0, a1, a2v, a3;
                ldsm4(a0, a1, a2v, a3, pa + kc * 32);
#pragma unroll
                for (int pr = 0; pr < 4; ++pr) {
                    uint32_t b0, b1, b2, b3;
                    ldsm4(b0, b1, b2, b3, pb + pr * (16 * XSTR * 4) + kc * 32);
                    asm volatile(
                        "mma.sync.aligned.m16n8k16.row.col.f32.f16.f16.f32 "
                        "{%0,%1,%2,%3}, {%4,%5,%6,%7}, {%8,%9}, {%0,%1,%2,%3};\n"
                        : "+f"(acc[2 * pr].x), "+f"(acc[2 * pr].y),
                          "+f"(acc[2 * pr].z), "+f"(acc[2 * pr].w)
                        : "r"(a0), "r"(a1), "r"(a2v), "r"(a3), "r"(b0), "r"(b1));
                    asm volatile(
                        "mma.sync.aligned.m16n8k16.row.col.f32.f16.f16.f32 "
                        "{%0,%1,%2,%3}, {%4,%5,%6,%7}, {%8,%9}, {%0,%1,%2,%3};\n"
                        : "+f"(acc[2 * pr + 1].x), "+f"(acc[2 * pr + 1].y),
                          "+f"(acc[2 * pr + 1].z), "+f"(acc[2 * pr + 1].w)
                        : "r"(a0), "r"(a1), "r"(a2v), "r"(a3), "r"(b2), "r"(b3));
                }
            }
        }
        __syncwarp();                    // warp's Ps reads done before rewrite

        if (jt < 63) {
            if (jt == 62) CP_WAIT(0); else CP_WAIT(1);   // own A(jt+1) arrived
            PSTAGE(jt + 1, nxt);
            uint32_t* Xn = (uint32_t*)sm + OFF_X + nxt * 2304;
            *(uint4*)&Xn[u0 * XSTR + ch0 * 4] = xv0;     // deferred X STS
            *(uint4*)&Xn[u1 * XSTR + ch1 * 4] = xv1;
        }
        __syncthreads();                 // Xs[nxt] ready; Xs[cur] readers done
    }

    // --- Z reduction ---
#pragma unroll
    for (int it = 0; it < 8; ++it) {
        float v = zp[it];
#pragma unroll
        for (int o = 8; o; o >>= 1) v += __shfl_xor_sync(0xffffffffu, v, o);
        if (c == 0) Zs[w * 16 + 8 * h + it] = v;
    }
    __syncwarp();

    // --- epilogue: relu(D / Z) ---
    float inv0 = 1.0f / Zs[w * 16 + g];
    float inv1 = 1.0f / Zs[w * 16 + g + 8];
    float* outb = out + ((size_t)b * NN + wrow0) * UU;
#pragma unroll
    for (int nb = 0; nb < 8; ++nb) {
        int col = nb * 8 + tig * 2;
        float2 v0 = make_float2(fmaxf(acc[nb].x * inv0, 0.f), fmaxf(acc[nb].y * inv0, 0.f));
        float2 v1 = make_float2(fmaxf(acc[nb].z * inv1, 0.f), fmaxf(acc[nb].w * inv1, 0.f));
        *(float2*)(outb + (size_t)g * UU + col) = v0;
        *(float2*)(outb + (size_t)(g + 8) * UU + col) = v1;
    }
#undef ISSUE_A
#undef PSTAGE
}

// ---------------------------------------------------------------------------
extern "C" void kernel_launch(void* const* d_in, const int* in_sizes, int n_in,
                              void* d_out, int out_size) {
    const float* H = (const float*)d_in[0];       // [8,4096,128]
    const float* Amask = (const float*)d_in[1];   // [8,4096,4096]
    const float* W = (const float*)d_in[2];       // [128,64]
    const float* a1 = (const float*)d_in[3];      // [64,1]
    const float* a2 = (const float*)d_in[4];      // [64,1]
    float* out = (float*)d_out;                   // [8,4096,64]

    cudaFuncSetAttribute(xgemm16_kernel, cudaFuncAttributeMaxDynamicSharedMemorySize, XG_SMEM);
    cudaFuncSetAttribute(gat_kernel, cudaFuncAttributeMaxDynamicSharedMemorySize, SMEM_GAT);

    wk_kernel<<<1, 128>>>(W, a1, a2);
    st2_kernel<<<512, 256>>>(H);
    xgemm16_kernel<<<(BATCH * NN) / 128, 256, XG_SMEM>>>(H, W);
    gat_kernel<<<dim3(NN / 128, BATCH), 256, SMEM_GAT>>>(Amask, out);
}